// round 9
// baseline (speedup 1.0000x reference)
#include <cuda_runtime.h>
#include <math.h>

#define NPB   120000                 // points per batch
#define NB    8                      // batches
#define NPTS  (NPB*NB)               // 960000
#define GX    704
#define GY    800
#define GZ    20
#define MAXV  40000
#define MAXP  10
#define SENT  0x7FFFFFFF

// Hash table: per-batch open addressing, 64-bit entry.
//   phase 1 (prep):  (leader_idx << 24) | lid
//   phase 2 (slot):  (1<<63) | (slot << 24) | lid      (slot = OVERCAP if rank >= MAXV)
#define HBITS 18
#define HSIZE (1 << HBITS)           // 262144 buckets per batch
#define HMASK (HSIZE - 1)
#define EMPTY 0xFFFFFFFFFFFFFFFFull
#define LIDMASK 0xFFFFFFull          // lid < 11,264,000 < 2^24
#define OVERCAP 0xFFFFF

#define CHUNK 1024                   // points per scan chunk
#define CPB   ((NPB + CHUNK - 1) / CHUNK)   // 118 chunks per batch
#define NBLK  (NB * CPB)                    // 944 blocks in k_slot

// Output layout (float32), concatenated in reference return order:
#define OFF_VOX 0                          // 8*40000*10*4 = 12,800,000
#define OFF_NP  12800000                   // 8*40000      =    320,000
#define OFF_CO  13120000                   // 8*40000*4    =  1,280,000
#define OFF_GS  14400000                   // 3

// Scratch (device globals; 16B-aligned via vector element types)
__device__ ulonglong2 g_hash2[(NB * HSIZE) / 2];        // 16 MB  (L2-resident)
__device__ int4       g_vox4 [(NB * MAXV * MAXP) / 4];  // 12.8 MB (L2-resident)
__device__ int        g_bkt  [NPTS];                    // bucket index per point (-1 invalid)
__device__ int        g_cnt  [NB * MAXV];               // points per voxel (uncapped)
__device__ unsigned   g_stat [NBLK];                    // lookback: state<<30 | sum

__device__ __forceinline__ unsigned hash_lid(int lid) {
    return ((unsigned)lid * 0x9E3779B1u) >> (32 - HBITS);
}

// K0: vectorized clear of hash + vox lists + counters + lookback + coors defaults + grid_size
__global__ void k_clear(float* __restrict__ out) {
    int i = blockIdx.x * blockDim.x + threadIdx.x;
    if (i < (NB * HSIZE) / 2)       g_hash2[i] = make_ulonglong2(EMPTY, EMPTY);
    if (i < (NB * MAXV * MAXP) / 4) g_vox4[i]  = make_int4(SENT, SENT, SENT, SENT);
    if (i < NB * MAXV) {
        g_cnt[i] = 0;
        float b = (float)(i / MAXV);
        ((float4*)(out + OFF_CO))[i] = make_float4(b, -1.f, -1.f, -1.f);
    }
    if (i < NBLK) g_stat[i] = 0u;
    if (i == 0) {
        out[OFF_GS + 0] = 704.0f;
        out[OFF_GS + 1] = 800.0f;
        out[OFF_GS + 2] = 20.0f;
    }
}

// K1: compute cell, hash-insert min point index per cell, remember bucket.
// Points staged through shared memory for fully coalesced global loads.
__global__ void __launch_bounds__(256) k_prep(const float* __restrict__ pts, int n) {
    __shared__ float sp[256 * 5];
    int blk0 = blockIdx.x * 256;          // first point of this block
    int t    = threadIdx.x;

    // cooperative coalesced load: 320 float4s = 1280 floats = 256 points
    const float4* src = (const float4*)(pts + (size_t)blk0 * 5);
    int nf4 = (n - blk0 >= 256) ? 320 : ((n - blk0) * 5 + 3) / 4;
    #pragma unroll
    for (int k = 0; k < 2; k++) {
        int q = t + k * 256;
        if (q < nf4) ((float4*)sp)[q] = src[q];
    }
    __syncthreads();

    int i = blk0 + t;
    if (i >= n) return;
    float x = sp[t*5 + 1];
    float y = sp[t*5 + 2];
    float z = sp[t*5 + 3];
    // match XLA: floor((p - pc_min) / vsize), IEEE division regardless of fast-math
    int cx = (int)floorf(__fdiv_rn(__fadd_rn(x,  0.0f), 0.1f));
    int cy = (int)floorf(__fdiv_rn(__fadd_rn(y, 40.0f), 0.1f));
    int cz = (int)floorf(__fdiv_rn(__fadd_rn(z,  3.0f), 0.2f));
    int bkt = -1;
    if (cx >= 0 && cx < GX && cy >= 0 && cy < GY && cz >= 0 && cz < GZ) {
        int lid = (cz * GY + cy) * GX + cx;
        int b   = i / NPB;
        int li  = i - b * NPB;
        unsigned long long* tab = (unsigned long long*)g_hash2 + (size_t)b * HSIZE;
        unsigned long long  pk  = ((unsigned long long)li << 24) | (unsigned)lid;
        unsigned h = hash_lid(lid);
        while (true) {
            unsigned long long cur = tab[h];
            if (cur == EMPTY) {
                unsigned long long old = atomicCAS(&tab[h], EMPTY, pk);
                if (old == EMPTY) break;        // claimed bucket
                cur = old;
            }
            if ((unsigned)(cur & LIDMASK) == (unsigned)(pk & LIDMASK)) {
                atomicMin(&tab[h], pk);         // same lid: min over point index
                break;
            }
            h = (h + 1) & HMASK;
        }
        bkt = (int)h;
    }
    g_bkt[i] = bkt;
}

// K2 (fused): leader flags -> decoupled-lookback scan -> slot assign (+coors) -> insert.
// One block per 1024-point chunk; 4 points per thread.
__global__ void __launch_bounds__(256) k_slot(float* __restrict__ out) {
    const int blk  = blockIdx.x;
    const int b    = blk / CPB, c = blk - b * CPB;
    const int t    = threadIdx.x;
    const int base = b * NPB + c * CHUNK;
    const int lim  = b * NPB + NPB;
    const int p0   = base + t * 4;
    unsigned long long* tab = (unsigned long long*)g_hash2 + (size_t)b * HSIZE;
    int* vox = (int*)g_vox4;

    // ---- Phase A: leader flags (full 64-bit compare: slot-form has bit 63 set,
    //      so a concurrently rewritten bucket can never alias a point index) ----
    int  bk[4];
    unsigned long long cur[4];
    int  f[4];
    int  cnt = 0;
    #pragma unroll
    for (int j = 0; j < 4; j++) {
        int i = p0 + j;
        f[j] = 0; bk[j] = -1;
        if (i < lim) {
            bk[j] = g_bkt[i];
            if (bk[j] >= 0) {
                cur[j] = tab[bk[j]];
                f[j] = ((cur[j] >> 24) == (unsigned long long)(i - b * NPB));
            }
        }
        cnt += f[j];
    }

    // ---- block exclusive scan of per-thread leader counts (8 warps) ----
    int lane = t & 31, wid = t >> 5;
    int v = cnt;
    #pragma unroll
    for (int o = 1; o < 32; o <<= 1) {
        int u = __shfl_up_sync(0xFFFFFFFFu, v, o);
        if (lane >= o) v += u;
    }
    __shared__ int ws[8];
    __shared__ int sh_total, sh_prefix;
    if (lane == 31) ws[wid] = v;
    __syncthreads();
    if (t == 0) {
        int s = 0;
        #pragma unroll
        for (int k = 0; k < 8; k++) { int tmp = ws[k]; ws[k] = s; s += tmp; }
        sh_total = s;
        // publish aggregate (or inclusive for chunk 0) ASAP
        unsigned st = ((c == 0 ? 2u : 1u) << 30) | (unsigned)s;
        atomicExch(&g_stat[blk], st);
    }
    __syncthreads();
    int run_excl = ws[wid] + (v - cnt);
    int total    = sh_total;

    // ---- Phase B: warp-parallel decoupled lookback (warp 0) ----
    if (c == 0) {
        if (t == 0) sh_prefix = 0;
    } else if (t < 32) {
        int prefix = 0;
        int p = c;
        while (p > 0) {
            int lo = p - 32; if (lo < 0) lo = 0;
            int idx = lo + t;
            bool act = idx < p;
            unsigned st = 0;
            if (act) {
                do { st = *(volatile unsigned*)&g_stat[b * CPB + idx]; }
                while ((st >> 30) == 0u);
            }
            unsigned mask2 = __ballot_sync(0xFFFFFFFFu, act && (st >> 30) == 2u);
            if (mask2) {
                int top = 31 - __clz(mask2);     // deepest lane with inclusive prefix
                int contrib = (act && t >= top) ? (int)(st & 0x3FFFFFFFu) : 0;
                prefix += __reduce_add_sync(0xFFFFFFFFu, contrib);
                break;
            } else {
                int contrib = act ? (int)(st & 0x3FFFFFFFu) : 0;
                prefix += __reduce_add_sync(0xFFFFFFFFu, contrib);
                p = lo;
            }
        }
        if (t == 0) {
            atomicExch(&g_stat[blk], (2u << 30) | (unsigned)(prefix + total));
            sh_prefix = prefix;
        }
    }
    __syncthreads();

    // ---- Phase C: assign slots to this chunk's leaders; leaders write coors ----
    int run = sh_prefix + run_excl;
    #pragma unroll
    for (int j = 0; j < 4; j++) {
        if (f[j]) {
            int slot = (run < MAXV) ? run : OVERCAP;
            unsigned lid = (unsigned)(cur[j] & LIDMASK);
            atomicExch(&tab[bk[j]],
                       (1ull << 63) | ((unsigned long long)slot << 24) | lid);
            if (slot < MAXV) {
                int x  = lid % GX;
                int t2 = lid / GX;
                int y  = t2 % GY;
                int z  = t2 / GY;
                ((float4*)(out + OFF_CO))[b * MAXV + slot] =
                    make_float4((float)b, (float)z, (float)y, (float)x);
            }
            run++;
        }
    }
    __syncthreads();   // same-chunk leaders assigned before same-chunk inserts

    // ---- Phase D: insert points + count. Leader chunk <= own chunk, so spinning
    //      on bit 63 only waits on lower block IDs (always scheduled no later). ----
    #pragma unroll
    for (int j = 0; j < 4; j++) {
        int i = p0 + j;
        if (i < lim && bk[j] >= 0) {
            unsigned long long e;
            do { e = *(volatile unsigned long long*)&tab[bk[j]]; }
            while (!(e >> 63));
            int slot = (int)((e >> 24) & 0xFFFFF);
            if (slot < MAXV) {
                atomicAdd(&g_cnt[b * MAXV + slot], 1);
                int* list = &vox[((size_t)b * MAXV + slot) * MAXP];
                int carry = i - b * NPB;
                #pragma unroll
                for (int q = 0; q < MAXP; q++) {
                    int old = atomicMin(&list[q], carry);
                    if (old == SENT) break;              // took empty tail slot
                    carry = (old > carry) ? old : carry; // displaced value moves right
                }
            }
        }
    }
}

// K3: 4 rows per thread -> 4 independent gathers in flight (MLP=4).
// int4 coalesced index load; 4 consecutive float4 stores per thread.
__global__ void __launch_bounds__(256) k_fill(const float* __restrict__ pts,
                                              float* __restrict__ out) {
    int i = blockIdx.x * blockDim.x + threadIdx.x;   // 800000 threads
    if (i < NB * MAXV) {   // num_points = min(count, MAXP)
        int c = g_cnt[i];
        out[OFF_NP + i] = (float)((c < MAXP) ? c : MAXP);
    }
    if (i >= (NB * MAXV * MAXP) / 4) return;

    int4 idx4 = ((const int4*)g_vox4)[i];            // 4 row indices, coalesced
    int b = (i * 4) / (MAXV * MAXP);                 // batch of row group
    const float* pb = pts + (size_t)b * NPB * 5 + 1;

    // issue all gathers before any store (4 independent chains)
    float4 r0 = make_float4(0.f,0.f,0.f,0.f), r1 = r0, r2 = r0, r3 = r0;
    if (idx4.x != SENT) { const float* p = pb + (size_t)idx4.x * 5; r0 = make_float4(p[0],p[1],p[2],p[3]); }
    if (idx4.y != SENT) { const float* p = pb + (size_t)idx4.y * 5; r1 = make_float4(p[0],p[1],p[2],p[3]); }
    if (idx4.z != SENT) { const float* p = pb + (size_t)idx4.z * 5; r2 = make_float4(p[0],p[1],p[2],p[3]); }
    if (idx4.w != SENT) { const float* p = pb + (size_t)idx4.w * 5; r3 = make_float4(p[0],p[1],p[2],p[3]); }

    float4* dst = (float4*)(out + OFF_VOX) + (size_t)i * 4;
    dst[0] = r0; dst[1] = r1; dst[2] = r2; dst[3] = r3;
}

extern "C" void kernel_launch(void* const* d_in, const int* in_sizes, int n_in,
                              void* d_out, int out_size) {
    const float* pts = (const float*)d_in[0];
    int n = in_sizes[0] / 5;                 // 960000
    float* out = (float*)d_out;

    const int T = 256;
    k_clear<<<((NB * HSIZE) / 2 + T - 1) / T, T>>>(out);   // 4096 blocks covers all clears
    k_prep <<<(n + T - 1) / T, T>>>(pts, n);
    k_slot <<<NBLK, T>>>(out);
    k_fill <<<((NB * MAXV * MAXP) / 4 + T - 1) / T, T>>>(pts, out);
}